// round 7
// baseline (speedup 1.0000x reference)
#include <cuda_runtime.h>
#include <cstdint>
#include <cstddef>

#define THREADS 128
#define TILE_ROWS 32
#define STRIDE 132                               // floats; 528B rows
#define TILE_SMEM_FLOATS (TILE_ROWS * STRIDE)
#define TILE_SMEM_BYTES (TILE_SMEM_FLOATS * 4)   // 16896
#define NTILES 16384                             // 8*256*256 / 32
#define EGRID 592                                // 4 * 148

__device__ float g_R2[8 * 256 * 128];     // Vx + 0.5*Ub  (1 MB)
__device__ float g_P2[8 * 16 * 32 * 2];   // packed B fragments oc0 (resident) / oc1 (stream)
__device__ float4 g_Q[4 * 16 * 32];       // packed B fragment pairs oc2,3 (stream)

__device__ __forceinline__ uint32_t f2tf32(float f) {
    uint32_t r;
    asm("cvt.rna.tf32.f32 %0, %1;" : "=r"(r) : "f"(f));
    return r;
}
__device__ __forceinline__ uint32_t smem_u32(const void* p) {
    uint32_t a;
    asm("{ .reg .u64 t; cvta.to.shared.u64 t, %1; cvt.u32.u64 %0, t; }" : "=r"(a) : "l"(p));
    return a;
}

// Stage one 32x128 fp32 tile into SMEM via cp.async.cg; ALWAYS commits a group.
__device__ __forceinline__ void stage_cp(uint32_t sdst, const float* __restrict__ src,
                                         int tid, bool pred) {
    if (pred) {
#pragma unroll
        for (int q = 0; q < 8; q++) {
            int idx = tid + q * THREADS;                   // 0..1023 x 16B
            uint32_t dst = sdst + (uint32_t)((idx >> 5) * (STRIDE * 4) + (idx & 31) * 16);
            asm volatile("cp.async.cg.shared.global [%0], [%1], 16;"
                         :: "r"(dst), "l"(src + (size_t)idx * 4) : "memory");
        }
    }
    asm volatile("cp.async.commit_group;" ::: "memory");
}

// ---------------------------------------------------------------------------
// Fused prep kernel. Blocks [0,128): Vx rows. Blocks [128,152): pack U_w.
//   Vx:   g_R2[b,n,o] = x[b,n,:].V_w[o,:] + V_b[o] + 0.5*U_b[o]
//   Pack: column-permuted tf32(rna) U_w fragments; o = w*32+8*(c>>1)+2*oc+(c&1)
//         so thread (g,tg) owns o-range [w*32+8*tg, +8) contiguously.
// ---------------------------------------------------------------------------
__global__ __launch_bounds__(256) void prep_kernel(
    const float* __restrict__ x,  const float* __restrict__ Vw,
    const float* __restrict__ Vb, const float* __restrict__ Ub,
    const float* __restrict__ Uw)
{
    if (blockIdx.x >= 128) {                     // ---- pack part ----
        int p = (blockIdx.x - 128) * 256 + threadIdx.x;   // 0..6143
        if (p < 4096) {
            int lane = p & 31, ks = (p >> 5) & 15, q = p >> 9;
            int w = q >> 1, oc = q & 1, g = lane >> 2;
            int row = w * 32 + 8 * (g >> 1) + 2 * oc + (g & 1);
            int k0  = ks * 8 + (lane & 3);
            g_P2[p * 2 + 0] = __uint_as_float(f2tf32(Uw[row * 128 + k0]));
            g_P2[p * 2 + 1] = __uint_as_float(f2tf32(Uw[row * 128 + k0 + 4]));
        } else {
            int r = p - 4096;
            int lane = r & 31, ks = (r >> 5) & 15, w = r >> 9;
            int g = lane >> 2;
            int row2 = w * 32 + 8 * (g >> 1) + 4 + (g & 1);   // oc=2
            int row3 = row2 + 2;                               // oc=3
            int k0   = ks * 8 + (lane & 3);
            g_Q[(w * 16 + ks) * 32 + lane] = make_float4(
                __uint_as_float(f2tf32(Uw[row2 * 128 + k0])),
                __uint_as_float(f2tf32(Uw[row2 * 128 + k0 + 4])),
                __uint_as_float(f2tf32(Uw[row3 * 128 + k0])),
                __uint_as_float(f2tf32(Uw[row3 * 128 + k0 + 4])));
        }
        return;
    }
    // ---- Vx part ----
    __shared__ float xs[16 * 128];
    int tid = threadIdx.x;
    int rbase = blockIdx.x * 16;
    const float4* xp = reinterpret_cast<const float4*>(x + rbase * 128);
    float4* xsp = reinterpret_cast<float4*>(xs);
#pragma unroll
    for (int q = 0; q < 2; q++) xsp[tid + q * 256] = xp[tid + q * 256];
    __syncthreads();

    int o  = tid & 127;
    int r0 = tid >> 7;
    float acc[8];
    float bias = Vb[o] + 0.5f * Ub[o];
#pragma unroll
    for (int k = 0; k < 8; k++) acc[k] = bias;
    const float4* wr = reinterpret_cast<const float4*>(Vw + o * 128);
#pragma unroll
    for (int h4 = 0; h4 < 32; h4++) {
        float4 w = wr[h4];
#pragma unroll
        for (int k = 0; k < 8; k++) {
            const float* xr = xs + (r0 + 2 * k) * 128 + h4 * 4;
            acc[k] += w.x * xr[0] + w.y * xr[1] + w.z * xr[2] + w.w * xr[3];
        }
    }
#pragma unroll
    for (int k = 0; k < 8; k++)
        g_R2[(rbase + r0 + 2 * k) * 128 + o] = acc[k];
}

// ---------------------------------------------------------------------------
// Edge kernel: tf32 mma.sync; 4 warps = 4 n-chunks of a 32-row tile.
//   out[m,o] = e[m,:].Uw[o,:] + R2[b,i,o] + R2[b,j,o]
// Grid-stride (chip-wide read locality); double-buffered cp.async;
// oc0 B resident, oc1/2/3 streamed (L1-resident); reg-prefetched bias;
// contiguous-o epilogue. 4 CTAs/SM.
// ---------------------------------------------------------------------------
__global__ __launch_bounds__(THREADS, 4) void edge_kernel(
    const float* __restrict__ e, float* __restrict__ out)
{
    extern __shared__ float smem[];
    const int tid  = threadIdx.x;
    const int lane = tid & 31;
    const int warp = tid >> 5;
    const int g    = lane >> 2;
    const int tg   = lane & 3;
    const int ob8  = warp * 32 + 8 * tg;     // thread's contiguous o-range start
    uint32_t sbase = smem_u32(smem);

    // Resident B fragments (oc0 only)
    uint32_t Bf[16][2];
#pragma unroll
    for (int ks = 0; ks < 16; ks++) {
        float2 v = *reinterpret_cast<const float2*>(
            g_P2 + (size_t)(((warp * 2) * 16 + ks) * 32 + lane) * 2);
        Bf[ks][0] = __float_as_uint(v.x);
        Bf[ks][1] = __float_as_uint(v.y);
    }
    const float2* P1 = reinterpret_cast<const float2*>(g_P2)
                       + ((size_t)(warp * 2 + 1) * 16) * 32 + lane;  // oc1 stream
    const float4* Qp = g_Q + (size_t)(warp * 16) * 32 + lane;        // oc2/3 stream

    const int G  = (int)gridDim.x;
    const int t0 = (int)blockIdx.x;
    stage_cp(sbase, e + (size_t)t0 * (TILE_ROWS * 128), tid, t0 < NTILES);

    int s = 0;
    for (int t = t0; t < NTILES; t += G, s++) {
        const int p = s & 1;
        const int base_m = t * TILE_ROWS;
        const int b  = base_m >> 16;
        const int i  = (base_m >> 8) & 255;
        const int j0 = base_m & 255;

        // ---- Prefetch bias rows into registers (overlap wait + mma) ----
        float4 Rp[4][2];
        {
            const float* Rbase = g_R2 + ((size_t)(b * 256 + j0) * 128 + ob8);
#pragma unroll
            for (int q = 0; q < 4; q++) {
                int row = (q >> 1) * 16 + (q & 1) * 8 + g;
                Rp[q][0] = *reinterpret_cast<const float4*>(Rbase + (size_t)row * 128);
                Rp[q][1] = *reinterpret_cast<const float4*>(Rbase + (size_t)row * 128 + 4);
            }
            const float* Ri = g_R2 + ((size_t)(b * 256 + i) * 128 + ob8);
            float4 s0 = *reinterpret_cast<const float4*>(Ri);
            float4 s1 = *reinterpret_cast<const float4*>(Ri + 4);
#pragma unroll
            for (int q = 0; q < 4; q++) {
                Rp[q][0].x += s0.x; Rp[q][0].y += s0.y; Rp[q][0].z += s0.z; Rp[q][0].w += s0.w;
                Rp[q][1].x += s1.x; Rp[q][1].y += s1.y; Rp[q][1].z += s1.z; Rp[q][1].w += s1.w;
            }
        }

        asm volatile("cp.async.wait_group 0;" ::: "memory");
        __syncthreads();
        {
            const int tn = t + G;
            stage_cp(sbase + (uint32_t)((p ^ 1) * TILE_SMEM_BYTES),
                     e + (size_t)tn * (TILE_ROWS * 128), tid, tn < NTILES);
        }

        const uint32_t* sA = reinterpret_cast<const uint32_t*>(smem + p * TILE_SMEM_FLOATS);
        float c[2][4][4];
#pragma unroll
        for (int mt = 0; mt < 2; mt++)
#pragma unroll
            for (int oc = 0; oc < 4; oc++)
#pragma unroll
                for (int q = 0; q < 4; q++) c[mt][oc][q] = 0.f;

#pragma unroll
        for (int ks = 0; ks < 16; ks++) {
            float2 b1 = P1[ks * 32];              // oc1 stream, L1-hit
            float4 bs = Qp[ks * 32];              // oc2/3 stream, L1-hit
            uint32_t B1[2] = { __float_as_uint(b1.x), __float_as_uint(b1.y) };
            uint32_t B2[2] = { __float_as_uint(bs.x), __float_as_uint(bs.y) };
            uint32_t B3[2] = { __float_as_uint(bs.z), __float_as_uint(bs.w) };
#pragma unroll
            for (int mt = 0; mt < 2; mt++) {
                const uint32_t* ap = sA + (mt * 16 + g) * STRIDE + ks * 8 + tg;
                uint32_t a0 = ap[0];              // raw fp32 bits; HMMA truncates
                uint32_t a1 = ap[8 * STRIDE];
                uint32_t a2 = ap[4];
                uint32_t a3 = ap[8 * STRIDE + 4];
                asm volatile(
                    "mma.sync.aligned.m16n8k8.row.col.f32.tf32.tf32.f32 "
                    "{%0,%1,%2,%3}, {%4,%5,%6,%7}, {%8,%9}, {%0,%1,%2,%3};"
                    : "+f"(c[mt][0][0]), "+f"(c[mt][0][1]),
                      "+f"(c[mt][0][2]), "+f"(c[mt][0][3])
                    : "r"(a0), "r"(a1), "r"(a2), "r"(a3),
                      "r"(Bf[ks][0]), "r"(Bf[ks][1]));
                asm volatile(
                    "mma.sync.aligned.m16n8k8.row.col.f32.tf32.tf32.f32 "
                    "{%0,%1,%2,%3}, {%4,%5,%6,%7}, {%8,%9}, {%0,%1,%2,%3};"
                    : "+f"(c[mt][1][0]), "+f"(c[mt][1][1]),
                      "+f"(c[mt][1][2]), "+f"(c[mt][1][3])
                    : "r"(a0), "r"(a1), "r"(a2), "r"(a3), "r"(B1[0]), "r"(B1[1]));
                asm volatile(
                    "mma.sync.aligned.m16n8k8.row.col.f32.tf32.tf32.f32 "
                    "{%0,%1,%2,%3}, {%4,%5,%6,%7}, {%8,%9}, {%0,%1,%2,%3};"
                    : "+f"(c[mt][2][0]), "+f"(c[mt][2][1]),
                      "+f"(c[mt][2][2]), "+f"(c[mt][2][3])
                    : "r"(a0), "r"(a1), "r"(a2), "r"(a3), "r"(B2[0]), "r"(B2[1]));
                asm volatile(
                    "mma.sync.aligned.m16n8k8.row.col.f32.tf32.tf32.f32 "
                    "{%0,%1,%2,%3}, {%4,%5,%6,%7}, {%8,%9}, {%0,%1,%2,%3};"
                    : "+f"(c[mt][3][0]), "+f"(c[mt][3][1]),
                      "+f"(c[mt][3][2]), "+f"(c[mt][3][3])
                    : "r"(a0), "r"(a1), "r"(a2), "r"(a3), "r"(B3[0]), "r"(B3[1]));
            }
        }

        // ---- Epilogue: contiguous 8-float slice per thread per row ----
#pragma unroll
        for (int q = 0; q < 4; q++) {
            const int mt = q >> 1;
            const int h2 = (q & 1) * 2;
            const int row = (q >> 1) * 16 + (q & 1) * 8 + g;
            float4 v0 = make_float4(c[mt][0][h2]     + Rp[q][0].x,
                                    c[mt][0][h2 + 1] + Rp[q][0].y,
                                    c[mt][1][h2]     + Rp[q][0].z,
                                    c[mt][1][h2 + 1] + Rp[q][0].w);
            float4 v1 = make_float4(c[mt][2][h2]     + Rp[q][1].x,
                                    c[mt][2][h2 + 1] + Rp[q][1].y,
                                    c[mt][3][h2]     + Rp[q][1].z,
                                    c[mt][3][h2 + 1] + Rp[q][1].w);
            float* op = out + ((size_t)(base_m + row) * 128 + ob8);
            *reinterpret_cast<float4*>(op)     = v0;
            *reinterpret_cast<float4*>(op + 4) = v1;
        }
    }
}

// ---------------------------------------------------------------------------
// Inputs (metadata order): x, e, U_w, U_b, V_w, V_b. Output fp32 [8,256,256,128].
// ---------------------------------------------------------------------------
extern "C" void kernel_launch(void* const* d_in, const int* in_sizes, int n_in,
                              void* d_out, int out_size) {
    const float* x  = (const float*)d_in[0];
    const float* e  = (const float*)d_in[1];
    const float* Uw = (const float*)d_in[2];
    const float* Ub = (const float*)d_in[3];
    const float* Vw = (const float*)d_in[4];
    const float* Vb = (const float*)d_in[5];
    float* out = (float*)d_out;

    cudaFuncSetAttribute(edge_kernel, cudaFuncAttributeMaxDynamicSharedMemorySize,
                         2 * TILE_SMEM_BYTES);

    prep_kernel<<<152, 256>>>(x, Vw, Vb, Ub, Uw);
    edge_kernel<<<EGRID, THREADS, 2 * TILE_SMEM_BYTES>>>(e, out);
}

// round 8
// speedup vs baseline: 1.1597x; 1.1597x over previous
#include <cuda_runtime.h>
#include <cstdint>
#include <cstddef>

#define THREADS 128
#define TILE_ROWS 32
#define STRIDE 132                               // floats; 528B rows
#define TILE_SMEM_FLOATS (TILE_ROWS * STRIDE)
#define TILE_SMEM_BYTES (TILE_SMEM_FLOATS * 4)   // 16896
#define NSTAGE 3
#define NTILES 16384                             // 8*256*256 / 32
#define EGRID 444                                // 3 * 148

__device__ float g_R2[8 * 256 * 128];     // Vx + 0.5*Ub  (1 MB)
__device__ float g_P2[8 * 16 * 32 * 2];   // resident B fragments (oc 0,1 per warp), 32 KB
__device__ float4 g_Q[4 * 16 * 32];       // streamed B fragment pairs (oc 2,3), 32 KB

__device__ __forceinline__ uint32_t f2tf32(float f) {
    uint32_t r;
    asm("cvt.rna.tf32.f32 %0, %1;" : "=r"(r) : "f"(f));
    return r;
}
__device__ __forceinline__ uint32_t smem_u32(const void* p) {
    uint32_t a;
    asm("{ .reg .u64 t; cvta.to.shared.u64 t, %1; cvt.u32.u64 %0, t; }" : "=r"(a) : "l"(p));
    return a;
}

// Stage one 32x128 fp32 tile into SMEM via cp.async.cg; ALWAYS commits a group.
__device__ __forceinline__ void stage_cp(uint32_t sdst, const float* __restrict__ src,
                                         int tid, bool pred) {
    if (pred) {
#pragma unroll
        for (int q = 0; q < 8; q++) {
            int idx = tid + q * THREADS;                   // 0..1023 x 16B
            uint32_t dst = sdst + (uint32_t)((idx >> 5) * (STRIDE * 4) + (idx & 31) * 16);
            asm volatile("cp.async.cg.shared.global [%0], [%1], 16;"
                         :: "r"(dst), "l"(src + (size_t)idx * 4) : "memory");
        }
    }
    asm volatile("cp.async.commit_group;" ::: "memory");
}

// ---------------------------------------------------------------------------
// Fused prep kernel. Blocks [0,128): Vx rows. Blocks [128,152): pack U_w.
// ---------------------------------------------------------------------------
__global__ __launch_bounds__(256) void prep_kernel(
    const float* __restrict__ x,  const float* __restrict__ Vw,
    const float* __restrict__ Vb, const float* __restrict__ Ub,
    const float* __restrict__ Uw)
{
    if (blockIdx.x >= 128) {                     // ---- pack part ----
        int p = (blockIdx.x - 128) * 256 + threadIdx.x;   // 0..6143
        if (p < 4096) {
            int lane = p & 31, ks = (p >> 5) & 15, q = p >> 9;
            int w = q >> 1, oc = q & 1, g = lane >> 2;
            int row = w * 32 + 8 * (g >> 1) + 2 * oc + (g & 1);
            int k0  = ks * 8 + (lane & 3);
            g_P2[p * 2 + 0] = __uint_as_float(f2tf32(Uw[row * 128 + k0]));
            g_P2[p * 2 + 1] = __uint_as_float(f2tf32(Uw[row * 128 + k0 + 4]));
        } else {
            int r = p - 4096;
            int lane = r & 31, ks = (r >> 5) & 15, w = r >> 9;
            int g = lane >> 2;
            int row2 = w * 32 + 8 * (g >> 1) + 4 + (g & 1);   // oc=2
            int row3 = row2 + 2;                               // oc=3
            int k0   = ks * 8 + (lane & 3);
            g_Q[(w * 16 + ks) * 32 + lane] = make_float4(
                __uint_as_float(f2tf32(Uw[row2 * 128 + k0])),
                __uint_as_float(f2tf32(Uw[row2 * 128 + k0 + 4])),
                __uint_as_float(f2tf32(Uw[row3 * 128 + k0])),
                __uint_as_float(f2tf32(Uw[row3 * 128 + k0 + 4])));
        }
        return;
    }
    // ---- Vx part ----
    __shared__ float xs[16 * 128];
    int tid = threadIdx.x;
    int rbase = blockIdx.x * 16;
    const float4* xp = reinterpret_cast<const float4*>(x + rbase * 128);
    float4* xsp = reinterpret_cast<float4*>(xs);
#pragma unroll
    for (int q = 0; q < 2; q++) xsp[tid + q * 256] = xp[tid + q * 256];
    __syncthreads();

    int o  = tid & 127;
    int r0 = tid >> 7;
    float acc[8];
    float bias = Vb[o] + 0.5f * Ub[o];
#pragma unroll
    for (int k = 0; k < 8; k++) acc[k] = bias;
    const float4* wr = reinterpret_cast<const float4*>(Vw + o * 128);
#pragma unroll
    for (int h4 = 0; h4 < 32; h4++) {
        float4 w = wr[h4];
#pragma unroll
        for (int k = 0; k < 8; k++) {
            const float* xr = xs + (r0 + 2 * k) * 128 + h4 * 4;
            acc[k] += w.x * xr[0] + w.y * xr[1] + w.z * xr[2] + w.w * xr[3];
        }
    }
#pragma unroll
    for (int k = 0; k < 8; k++)
        g_R2[(rbase + r0 + 2 * k) * 128 + o] = acc[k];
}

// ---------------------------------------------------------------------------
// Edge kernel (round-5 structure + ldmatrix.x4 A-fragment loads).
//   out[m,o] = e[m,:].Uw[o,:] + R2[b,i,o] + R2[b,j,o]
// ---------------------------------------------------------------------------
__global__ __launch_bounds__(THREADS, 3) void edge_kernel(
    const float* __restrict__ e, float* __restrict__ out)
{
    extern __shared__ float smem[];
    const int tid  = threadIdx.x;
    const int lane = tid & 31;
    const int warp = tid >> 5;
    const int g    = lane >> 2;
    const int tg   = lane & 3;
    const int ob8  = warp * 32 + 8 * tg;     // thread's contiguous o-range start
    uint32_t sbase = smem_u32(smem);

    // ldmatrix per-lane byte offset: matrix (lane>>3): 0:a0 rows 0-7 col+0,
    // 1:a1 rows 8-15 col+0, 2:a2 rows 0-7 col+4, 3:a3 rows 8-15 col+4.
    const uint32_t lmoff =
        (uint32_t)(((((lane >> 3) & 1) * 8 + (lane & 7)) * STRIDE + (lane >> 4) * 4) * 4);

    // Resident B fragments (oc 0,1): coalesced one-time loads
    uint32_t Bf[2][16][2];
#pragma unroll
    for (int oc = 0; oc < 2; oc++)
#pragma unroll
        for (int ks = 0; ks < 16; ks++) {
            float2 v = *reinterpret_cast<const float2*>(
                g_P2 + (size_t)(((warp * 2 + oc) * 16 + ks) * 32 + lane) * 2);
            Bf[oc][ks][0] = __float_as_uint(v.x);
            Bf[oc][ks][1] = __float_as_uint(v.y);
        }
    const float4* Qp = g_Q + (size_t)(warp * 16) * 32 + lane;

    const int G  = (int)gridDim.x;
    const int t0 = (int)blockIdx.x;
    stage_cp(sbase, e + (size_t)t0 * (TILE_ROWS * 128), tid, true);
    {
        const int t1 = t0 + G;
        stage_cp(sbase + TILE_SMEM_BYTES,
                 e + (size_t)t1 * (TILE_ROWS * 128), tid, t1 < NTILES);
    }

    int s = 0;
    for (int t = t0; t < NTILES; t += G, s++) {
        const int buf = s % NSTAGE;
        const int base_m = t * TILE_ROWS;
        const int b  = base_m >> 16;
        const int i  = (base_m >> 8) & 255;
        const int j0 = base_m & 255;

        // ---- Prefetch bias rows into registers (overlap wait + mma) ----
        float4 Rp[4][2];
        {
            const float* Rbase = g_R2 + ((size_t)(b * 256 + j0) * 128 + ob8);
#pragma unroll
            for (int q = 0; q < 4; q++) {
                int row = (q >> 1) * 16 + (q & 1) * 8 + g;
                Rp[q][0] = *reinterpret_cast<const float4*>(Rbase + (size_t)row * 128);
                Rp[q][1] = *reinterpret_cast<const float4*>(Rbase + (size_t)row * 128 + 4);
            }
            const float* Ri = g_R2 + ((size_t)(b * 256 + i) * 128 + ob8);
            float4 s0 = *reinterpret_cast<const float4*>(Ri);
            float4 s1 = *reinterpret_cast<const float4*>(Ri + 4);
#pragma unroll
            for (int q = 0; q < 4; q++) {
                Rp[q][0].x += s0.x; Rp[q][0].y += s0.y; Rp[q][0].z += s0.z; Rp[q][0].w += s0.w;
                Rp[q][1].x += s1.x; Rp[q][1].y += s1.y; Rp[q][1].z += s1.z; Rp[q][1].w += s1.w;
            }
        }

        asm volatile("cp.async.wait_group 1;" ::: "memory");
        __syncthreads();
        {
            const int tn = t + 2 * G;
            stage_cp(sbase + (uint32_t)(((s + 2) % NSTAGE) * TILE_SMEM_BYTES),
                     e + (size_t)(t + 2 * G) * (TILE_ROWS * 128), tid, tn < NTILES);
        }

        const uint32_t abase = sbase + (uint32_t)(buf * TILE_SMEM_BYTES) + lmoff;
        float c[2][4][4];
#pragma unroll
        for (int mt = 0; mt < 2; mt++)
#pragma unroll
            for (int oc = 0; oc < 4; oc++)
#pragma unroll
                for (int q = 0; q < 4; q++) c[mt][oc][q] = 0.f;

#pragma unroll
        for (int ks = 0; ks < 16; ks++) {
            float4 bs = Qp[ks * 32];              // streamed oc2/oc3 pair, L1-hit
            uint32_t B2[2] = { __float_as_uint(bs.x), __float_as_uint(bs.y) };
            uint32_t B3[2] = { __float_as_uint(bs.z), __float_as_uint(bs.w) };
#pragma unroll
            for (int mt = 0; mt < 2; mt++) {
                uint32_t a0, a1, a2, a3;
                uint32_t addr = abase + (uint32_t)((mt * 16 * STRIDE + ks * 8) * 4);
                asm volatile(
                    "ldmatrix.sync.aligned.m8n8.x4.shared.b16 {%0,%1,%2,%3}, [%4];"
                    : "=r"(a0), "=r"(a1), "=r"(a2), "=r"(a3) : "r"(addr));
#pragma unroll
                for (int oc = 0; oc < 2; oc++)
                    asm volatile(
                        "mma.sync.aligned.m16n8k8.row.col.f32.tf32.tf32.f32 "
                        "{%0,%1,%2,%3}, {%4,%5,%6,%7}, {%8,%9}, {%0,%1,%2,%3};"
                        : "+f"(c[mt][oc][0]), "+f"(c[mt][oc][1]),
                          "+f"(c[mt][oc][2]), "+f"(c[mt][oc][3])
                        : "r"(a0), "r"(a1), "r"(a2), "r"(a3),
                          "r"(Bf[oc][ks][0]), "r"(Bf[oc][ks][1]));
                asm volatile(
                    "mma.sync.aligned.m16n8k8.row.col.f32.tf32.tf32.f32 "
                    "{%0,%1,%2,%3}, {%4,%5,%6,%7}, {%8,%9}, {%0,%1,%2,%3};"
                    : "+f"(c[mt][2][0]), "+f"(c[mt][2][1]),
                      "+f"(c[mt][2][2]), "+f"(c[mt][2][3])
                    : "r"(a0), "r"(a1), "r"(a2), "r"(a3), "r"(B2[0]), "r"(B2[1]));
                asm volatile(
                    "mma.sync.aligned.m16n8k8.row.col.f32.tf32.tf32.f32 "
                    "{%0,%1,%2,%3}, {%4,%5,%6,%7}, {%8,%9}, {%0,%1,%2,%3};"
                    : "+f"(c[mt][3][0]), "+f"(c[mt][3][1]),
                      "+f"(c[mt][3][2]), "+f"(c[mt][3][3])
                    : "r"(a0), "r"(a1), "r"(a2), "r"(a3), "r"(B3[0]), "r"(B3[1]));
            }
        }

        // ---- Epilogue: contiguous 8-float slice per thread per row ----
#pragma unroll
        for (int q = 0; q < 4; q++) {
            const int mt = q >> 1;
            const int h2 = (q & 1) * 2;
            const int row = (q >> 1) * 16 + (q & 1) * 8 + g;
            float4 v0 = make_float4(c[mt][0][h2]     + Rp[q][0].x,
                                    c[mt][0][h2 + 1] + Rp[q][0].y,
                                    c[mt][1][h2]     + Rp[q][0].z,
                                    c[mt][1][h2 + 1] + Rp[q][0].w);
            float4 v1 = make_float4(c[mt][2][h2]     + Rp[q][1].x,
                                    c[mt][2][h2 + 1] + Rp[q][1].y,
                                    c[mt][3][h2]     + Rp[q][1].z,
                                    c[mt][3][h2 + 1] + Rp[q][1].w);
            float* op = out + ((size_t)(base_m + row) * 128 + ob8);
            *reinterpret_cast<float4*>(op)     = v0;
            *reinterpret_cast<float4*>(op + 4) = v1;
        }
    }
}

// ---------------------------------------------------------------------------
// Inputs (metadata order): x, e, U_w, U_b, V_w, V_b. Output fp32 [8,256,256,128].
// ---------------------------------------------------------------------------
extern "C" void kernel_launch(void* const* d_in, const int* in_sizes, int n_in,
                              void* d_out, int out_size) {
    const float* x  = (const float*)d_in[0];
    const float* e  = (const float*)d_in[1];
    const float* Uw = (const float*)d_in[2];
    const float* Ub = (const float*)d_in[3];
    const float* Vw = (const float*)d_in[4];
    const float* Vb = (const float*)d_in[5];
    float* out = (float*)d_out;

    cudaFuncSetAttribute(edge_kernel, cudaFuncAttributeMaxDynamicSharedMemorySize,
                         NSTAGE * TILE_SMEM_BYTES);

    prep_kernel<<<152, 256>>>(x, Vw, Vb, Ub, Uw);
    edge_kernel<<<EGRID, THREADS, NSTAGE * TILE_SMEM_BYTES>>>(e, out);
}